// round 15
// baseline (speedup 1.0000x reference)
#include <cuda_runtime.h>
#include <cstdint>

#define NN 100000
#define EE 1600000
#define CC 128
#define EPS_ 1e-5f
#define NBLK ((NN + 255) / 256)   // 391

// ---------------- scratch ----------------
__device__ __align__(16) float g_h[(size_t)NN * CC];
__device__ __align__(16) float g_agg[(size_t)NN * CC];
__device__ __align__(16) float g_x1[(size_t)NN * CC];
__device__ float g_dinv[NN];
__device__ float g_as[NN];
__device__ float g_ad[NN];
__device__ float g_stats[2 * CC];
__device__ float g_normA[CC];
__device__ float g_normB[CC];
__device__ int g_is64;
__device__ int g_degc[NN];
__device__ int g_rowstart[NN];
__device__ int g_cur[NN];
__device__ int g_bsum[NBLK + 1];
__device__ int g_boff[NBLK + 1];
__device__ int g_csrc[EE];
__device__ __align__(16) unsigned g_Whi[16384];
__device__ __align__(16) unsigned g_Wlo[16384];

// ---------------- edges dtype detection ----------------
__global__ void detect_dtype(const int* __restrict__ e32) {
    __shared__ int ok[256];
    int t = threadIdx.x;
    int all0 = 1;
#pragma unroll
    for (int i = 0; i < 2; i++) {
        int idx = 2 * (t + i * 256) + 1;
        if (e32[idx] != 0) all0 = 0;
    }
    ok[t] = all0;
    __syncthreads();
    for (int s = 128; s; s >>= 1) {
        if (t < s) ok[t] &= ok[t + s];
        __syncthreads();
    }
    if (t == 0) g_is64 = ok[0];
}

__device__ __forceinline__ int edge_src(const int* __restrict__ e32, int t) {
    return g_is64 ? e32[2 * t] : e32[t];
}
__device__ __forceinline__ int edge_dst(const int* __restrict__ e32, int t) {
    return g_is64 ? e32[2 * (EE + t)] : e32[EE + t];
}

// ---------------- CSR build ----------------
__global__ void zero_counts() {
    int i = blockIdx.x * blockDim.x + threadIdx.x;
    if (i < NN) g_degc[i] = 0;
}

__global__ void count_deg_kernel(const int* __restrict__ e32) {
    int t = blockIdx.x * blockDim.x + threadIdx.x;
    if (t < EE) atomicAdd(&g_degc[edge_dst(e32, t)], 1);
}

__global__ void dinv_kernel() {
    int i = blockIdx.x * blockDim.x + threadIdx.x;
    if (i < NN) g_dinv[i] = rsqrtf((float)(g_degc[i] + 1));
}

__global__ void scan1() {
    __shared__ int sm[256];
    int b = blockIdx.x, t = threadIdx.x;
    int idx = b * 256 + t;
    int v = (idx < NN) ? g_degc[idx] : 0;
    sm[t] = v;
    __syncthreads();
    for (int o = 1; o < 256; o <<= 1) {
        int add = (t >= o) ? sm[t - o] : 0;
        __syncthreads();
        sm[t] += add;
        __syncthreads();
    }
    if (idx < NN) g_rowstart[idx] = sm[t] - v;
    if (t == 255) g_bsum[b] = sm[255];
}

__global__ void scan2() {
    __shared__ int sm[512];
    int t = threadIdx.x;
    int v = (t < NBLK) ? g_bsum[t] : 0;
    sm[t] = v;
    __syncthreads();
    for (int o = 1; o < 512; o <<= 1) {
        int add = (t >= o) ? sm[t - o] : 0;
        __syncthreads();
        sm[t] += add;
        __syncthreads();
    }
    if (t < NBLK) g_boff[t] = sm[t] - v;
}

__global__ void scan3() {
    int idx = blockIdx.x * blockDim.x + threadIdx.x;
    if (idx < NN) {
        g_rowstart[idx] += g_boff[blockIdx.x];
        g_cur[idx] = 0;
    }
}

__global__ void fill_csr(const int* __restrict__ e32) {
    int t = blockIdx.x * blockDim.x + threadIdx.x;
    if (t >= EE) return;
    int s = edge_src(e32, t);
    int d = edge_dst(e32, t);
    int pos = g_rowstart[d] + atomicAdd(&g_cur[d], 1);
    g_csrc[pos] = s;
}

// ---------------- stats helpers ----------------
__global__ void zero_stats() {
    int i = threadIdx.x;
    if (i < 2 * CC) g_stats[i] = 0.f;
}

// per-channel affine for GraphNorm+bias: y = A*agg + B
__global__ void prep_norm(const float* __restrict__ bias, const float* __restrict__ gw,
                          const float* __restrict__ gb, const float* __restrict__ gms) {
    int c = threadIdx.x;
    const float invn = 1.0f / (float)NN;
    float s1 = g_stats[c] * invn;          // mean of raw agg
    float m2 = g_stats[128 + c] * invn;    // E[agg^2]
    float b = bias[c];
    float mean = s1 + b;
    float Et2 = m2 + 2.f * b * s1 + b * b;
    float a = gms[c] * mean;
    float var = Et2 - 2.f * a * mean + a * a;
    float A = gw[c] * rsqrtf(var + EPS_);
    g_normA[c] = A;
    g_normB[c] = A * (b - a) + gb[c];
}

// ---------------- TF32 GEMM ----------------
#define MMA_TF32(c, a, b) \
    asm volatile("mma.sync.aligned.m16n8k8.row.col.f32.tf32.tf32.f32 " \
                 "{%0,%1,%2,%3},{%4,%5,%6,%7},{%8,%9},{%0,%1,%2,%3};" \
                 : "+f"((c)[0]), "+f"((c)[1]), "+f"((c)[2]), "+f"((c)[3]) \
                 : "r"((a)[0]), "r"((a)[1]), "r"((a)[2]), "r"((a)[3]), \
                   "r"((b)[0]), "r"((b)[1]))

__device__ __forceinline__ void tf32_split(float v, unsigned& hi, unsigned& lo) {
    asm("cvt.rna.tf32.f32 %0, %1;" : "=r"(hi) : "f"(v));
    float rem = v - __uint_as_float(hi);
    asm("cvt.rna.tf32.f32 %0, %1;" : "=r"(lo) : "f"(rem));
}

__global__ void split_W(const float* __restrict__ W) {
    int slot = blockIdx.x * 256 + threadIdx.x;   // 0..16383
    int rg = slot & 1;
    int lane = (slot >> 1) & 31;
    int nt = (slot >> 6) & 15;
    int kc = slot >> 10;
    int k = kc * 8 + rg * 4 + (lane & 3);
    int n = nt * 8 + (lane >> 2);
    unsigned hi, lo;
    tf32_split(W[k * 128 + n], hi, lo);
    g_Whi[slot] = hi;
    g_Wlo[slot] = lo;
}

__device__ __forceinline__ float leaky01(float v) {
    return (v >= 0.f) ? v : 0.01f * v;
}

// GEMM: 64-row tile, smem-staged A, pre-split W, 2 CTAs/SM.
// FUSED: loader computes x1 = x + leaky(A*agg + B), writes g_x1, stages x1.
template <bool FUSED>
__device__ __forceinline__ void gemm_tf32_body(const float* __restrict__ X) {
    __shared__ float sX[64 * 68];   // 17.4 KB
    int row0 = blockIdx.x * 64;
    int tid = threadIdx.x;
    int w = tid >> 5, lane = tid & 31;
    int wm = w & 1, wn = w >> 1;
    int grp = lane >> 2, four = lane & 3;

    float acc[2][4][4];
#pragma unroll
    for (int mt = 0; mt < 2; mt++)
#pragma unroll
        for (int nt = 0; nt < 4; nt++)
#pragma unroll
            for (int c = 0; c < 4; c++) acc[mt][nt][c] = 0.f;

    int lr_base = wm * 32 + grp;

#pragma unroll
    for (int kch = 0; kch < 2; kch++) {
#pragma unroll
        for (int i = 0; i < 4; i++) {
            int idx = tid + i * 256;      // 0..1023
            int r = idx >> 4;             // 0..63
            int c4 = idx & 15;            // 0..15
            int gr = row0 + r;
            float4 v;
            if (!FUSED) {
                v = (gr < NN) ? ((const float4*)(X + (size_t)gr * 128 + kch * 64))[c4]
                              : make_float4(0.f, 0.f, 0.f, 0.f);
            } else {
                int cb = kch * 64 + c4 * 4;
                if (gr < NN) {
                    float4 av = ((const float4*)(g_agg + (size_t)gr * 128 + kch * 64))[c4];
                    float4 xv = ((const float4*)(X + (size_t)gr * 128 + kch * 64))[c4];
                    float4 A4 = *(const float4*)(g_normA + cb);
                    float4 B4 = *(const float4*)(g_normB + cb);
                    v.x = xv.x + leaky01(fmaf(A4.x, av.x, B4.x));
                    v.y = xv.y + leaky01(fmaf(A4.y, av.y, B4.y));
                    v.z = xv.z + leaky01(fmaf(A4.z, av.z, B4.z));
                    v.w = xv.w + leaky01(fmaf(A4.w, av.w, B4.w));
                    *(float4*)(g_x1 + (size_t)gr * 128 + cb) = v;
                } else {
                    v = make_float4(0.f, 0.f, 0.f, 0.f);
                }
            }
            *(float4*)(sX + r * 68 + c4 * 4) = v;
        }
        __syncthreads();

#pragma unroll
        for (int kc2 = 0; kc2 < 8; kc2++) {
            int kc = kch * 8 + kc2;
            unsigned bhi[4][2], blo[4][2];
#pragma unroll
            for (int nt = 0; nt < 4; nt++) {
                int ntg = wn * 4 + nt;
                int base = (kc * 16 + ntg) * 32 + lane;
                *(uint2*)bhi[nt] = ((const uint2*)g_Whi)[base];
                *(uint2*)blo[nt] = ((const uint2*)g_Wlo)[base];
            }
            int colb = kc2 * 8 + four;
#pragma unroll
            for (int mt = 0; mt < 2; mt++) {
                int r0 = lr_base + mt * 16;
                int r1 = r0 + 8;
                float f0 = sX[r0 * 68 + colb];
                float f1 = sX[r1 * 68 + colb];
                float f2 = sX[r0 * 68 + colb + 4];
                float f3 = sX[r1 * 68 + colb + 4];
                unsigned ahi[4], alo[4];
                tf32_split(f0, ahi[0], alo[0]);
                tf32_split(f1, ahi[1], alo[1]);
                tf32_split(f2, ahi[2], alo[2]);
                tf32_split(f3, ahi[3], alo[3]);
#pragma unroll
                for (int nt = 0; nt < 4; nt++) {
                    MMA_TF32(acc[mt][nt], ahi, bhi[nt]);
                    MMA_TF32(acc[mt][nt], alo, bhi[nt]);
                    MMA_TF32(acc[mt][nt], ahi, blo[nt]);
                }
            }
        }
        __syncthreads();
    }

#pragma unroll
    for (int mt = 0; mt < 2; mt++) {
        int r0 = row0 + lr_base + mt * 16;
        int r1 = r0 + 8;
#pragma unroll
        for (int nt = 0; nt < 4; nt++) {
            int coln = wn * 32 + nt * 8 + four * 2;
            if (r0 < NN)
                *(float2*)(g_h + (size_t)r0 * 128 + coln) = make_float2(acc[mt][nt][0], acc[mt][nt][1]);
            if (r1 < NN)
                *(float2*)(g_h + (size_t)r1 * 128 + coln) = make_float2(acc[mt][nt][2], acc[mt][nt][3]);
        }
    }
}

__global__ void __launch_bounds__(256, 2) gemm_tf32_A(const float* __restrict__ X) {
    gemm_tf32_body<false>(X);
}
// fused: GraphNorm-affine + leaky + residual on the fly (phase A finalize)
__global__ void __launch_bounds__(256, 2) gemm_tf32_B(const float* __restrict__ X) {
    gemm_tf32_body<true>(X);
}

// ---------------- stats epilogue (shared by both gathers) ----------------
// each warp owns one full output row (float4/lane); block-reduce into g_stats
__device__ __forceinline__ void stats_epilogue(float4 acc, int wid, int lane, int tid) {
    __shared__ float sm1[8][128];
    __shared__ float sm2[8][128];
    ((float4*)sm1[wid])[lane] = acc;
    float4 sq = make_float4(acc.x * acc.x, acc.y * acc.y, acc.z * acc.z, acc.w * acc.w);
    ((float4*)sm2[wid])[lane] = sq;
    __syncthreads();
    int ch = tid & 127;
    int st = tid >> 7;
    float s = 0.f;
    if (st == 0) {
#pragma unroll
        for (int w = 0; w < 8; w++) s += sm1[w][ch];
        atomicAdd(&g_stats[ch], s);
    } else {
#pragma unroll
        for (int w = 0; w < 8; w++) s += sm2[w][ch];
        atomicAdd(&g_stats[128 + ch], s);
    }
}

// ---------------- GCN gather: warp per dst, lane-cached edges + stats ----------------
__global__ void __launch_bounds__(256) gather_gcn() {
    int tid = threadIdx.x;
    int wid = tid >> 5;
    int lane = tid & 31;
    int d = blockIdx.x * 8 + wid;            // exact: 12500*8 == NN
    int beg = g_rowstart[d];
    int deg = g_degc[d];
    float dd = g_dinv[d];

    int s_l = (lane < deg) ? g_csrc[beg + lane] : 0;
    float w_l = (lane < deg) ? g_dinv[s_l] * dd : 0.f;

    float4 acc = ((const float4*)(g_h + (size_t)d * 128))[lane];
    float w0 = dd * dd;
    acc.x *= w0; acc.y *= w0; acc.z *= w0; acc.w *= w0;

    int n32 = deg < 32 ? deg : 32;
    for (int j = 0; j < n32; j++) {
        int s = __shfl_sync(0xffffffffu, s_l, j);
        float w = __shfl_sync(0xffffffffu, w_l, j);
        float4 v = ((const float4*)(g_h + (size_t)s * 128))[lane];
        acc.x = fmaf(v.x, w, acc.x);
        acc.y = fmaf(v.y, w, acc.y);
        acc.z = fmaf(v.z, w, acc.z);
        acc.w = fmaf(v.w, w, acc.w);
    }
    for (int j = beg + 32; j < beg + deg; j++) {
        int s = g_csrc[j];
        float w = g_dinv[s] * dd;
        float4 v = ((const float4*)(g_h + (size_t)s * 128))[lane];
        acc.x = fmaf(v.x, w, acc.x);
        acc.y = fmaf(v.y, w, acc.y);
        acc.z = fmaf(v.z, w, acc.z);
        acc.w = fmaf(v.w, w, acc.w);
    }
    __stwt(((float4*)(g_agg + (size_t)d * 128)) + lane, acc);
    stats_epilogue(acc, wid, lane, tid);
}

// ---------------- finalize B: affine norm + leaky + residual -> out ----------------
__global__ void finalize_B(float* __restrict__ xout) {
    int idx = blockIdx.x * blockDim.x + threadIdx.x;
    if (idx >= NN * CC) return;
    int c = idx & 127;
    float y = leaky01(fmaf(g_normA[c], g_agg[idx], g_normB[c]));
    xout[idx] = g_x1[idx] + y;
}

// ---------------- GAT attention dots ----------------
__global__ void attndot(const float* __restrict__ att_src, const float* __restrict__ att_dst) {
    int warp = (blockIdx.x * blockDim.x + threadIdx.x) >> 5;
    if (warp >= NN) return;
    int lane = threadIdx.x & 31;
    float4 hv = ((const float4*)(g_h + (size_t)warp * 128))[lane];
    float4 av = ((const float4*)att_src)[lane];
    float4 dv = ((const float4*)att_dst)[lane];
    float ps = hv.x * av.x + hv.y * av.y + hv.z * av.z + hv.w * av.w;
    float pd = hv.x * dv.x + hv.y * dv.y + hv.z * dv.z + hv.w * dv.w;
#pragma unroll
    for (int o = 16; o; o >>= 1) {
        ps += __shfl_xor_sync(0xffffffffu, ps, o);
        pd += __shfl_xor_sync(0xffffffffu, pd, o);
    }
    if (lane == 0) {
        g_as[warp] = ps;
        g_ad[warp] = pd;
    }
}

// ---------------- GAT gather (fused softmax, lane-cached) + stats ----------------
__global__ void __launch_bounds__(256) gather_gat() {
    int tid = threadIdx.x;
    int wid = tid >> 5;
    int lane = tid & 31;
    int d = blockIdx.x * 8 + wid;
    int beg = g_rowstart[d];
    int deg = g_degc[d];
    float add = g_ad[d];
    float es = g_as[d] + add;
    es = (es >= 0.f) ? es : 0.2f * es;

    int s_l = (lane < deg) ? g_csrc[beg + lane] : 0;
    float e_l = -3.4e38f;
    if (lane < deg) {
        float e = g_as[s_l] + add;
        e_l = (e >= 0.f) ? e : 0.2f * e;
    }

    float m = fmaxf(es, e_l);
    for (int j = beg + 32 + lane; j < beg + deg; j += 32) {
        float e = g_as[g_csrc[j]] + add;
        e = (e >= 0.f) ? e : 0.2f * e;
        m = fmaxf(m, e);
    }
#pragma unroll
    for (int o = 16; o; o >>= 1) m = fmaxf(m, __shfl_xor_sync(0xffffffffu, m, o));

    float ex_l = (lane < deg) ? __expf(e_l - m) : 0.f;
    float part = ex_l;
    for (int j = beg + 32 + lane; j < beg + deg; j += 32) {
        float e = g_as[g_csrc[j]] + add;
        e = (e >= 0.f) ? e : 0.2f * e;
        part += __expf(e - m);
    }
#pragma unroll
    for (int o = 16; o; o >>= 1) part += __shfl_xor_sync(0xffffffffu, part, o);
    float ws = __expf(es - m);
    float rden = 1.0f / (part + ws);

    float4 acc = ((const float4*)(g_h + (size_t)d * 128))[lane];
    acc.x *= ws; acc.y *= ws; acc.z *= ws; acc.w *= ws;
    int n32 = deg < 32 ? deg : 32;
    for (int j = 0; j < n32; j++) {
        int s = __shfl_sync(0xffffffffu, s_l, j);
        float w = __shfl_sync(0xffffffffu, ex_l, j);
        float4 v = ((const float4*)(g_h + (size_t)s * 128))[lane];
        acc.x = fmaf(v.x, w, acc.x);
        acc.y = fmaf(v.y, w, acc.y);
        acc.z = fmaf(v.z, w, acc.z);
        acc.w = fmaf(v.w, w, acc.w);
    }
    for (int j = beg + 32; j < beg + deg; j++) {
        int s = g_csrc[j];
        float e = g_as[s] + add;
        e = (e >= 0.f) ? e : 0.2f * e;
        float w = __expf(e - m);
        float4 v = ((const float4*)(g_h + (size_t)s * 128))[lane];
        acc.x = fmaf(v.x, w, acc.x);
        acc.y = fmaf(v.y, w, acc.y);
        acc.z = fmaf(v.z, w, acc.z);
        acc.w = fmaf(v.w, w, acc.w);
    }
    acc.x *= rden; acc.y *= rden; acc.z *= rden; acc.w *= rden;
    __stwt(((float4*)(g_agg + (size_t)d * 128)) + lane, acc);
    stats_epilogue(acc, wid, lane, tid);
}

// ---------------- launch ----------------
extern "C" void kernel_launch(void* const* d_in, const int* in_sizes, int n_in,
                              void* d_out, int out_size) {
    const float* x = (const float*)d_in[0];
    const int* e32 = (const int*)d_in[1];
    const float* W1 = (const float*)d_in[2];
    const float* b1 = (const float*)d_in[3];
    const float* gn_w = (const float*)d_in[4];
    const float* gn_b = (const float*)d_in[5];
    const float* gn_ms = (const float*)d_in[6];
    const float* Wg = (const float*)d_in[7];
    const float* bg = (const float*)d_in[8];
    const float* att_src = (const float*)d_in[9];
    const float* att_dst = (const float*)d_in[10];
    float* out = (float*)d_out;

    const int TPB = 256;
    const int nb_node = NBLK;
    const int nb_edge = (EE + TPB - 1) / TPB;
    const int nb_warp_node = (NN * 32 + TPB - 1) / TPB;   // 12500 exact
    const int nb_elem = (NN * CC + TPB - 1) / TPB;
    const int gemm_blocks = (NN + 63) / 64;

    // position GEMM at launch #4 so ncu (-s 5 -c 1) profiles it
    detect_dtype<<<1, 256>>>(e32);                 // 1
    zero_counts<<<nb_node, TPB>>>();               // 2
    split_W<<<64, 256>>>(W1);                      // 3
    gemm_tf32_A<<<gemm_blocks, 256>>>(x);          // 4  <-- profiled
    count_deg_kernel<<<nb_edge, TPB>>>(e32);       // 5
    dinv_kernel<<<nb_node, TPB>>>();
    scan1<<<nb_node, 256>>>();
    scan2<<<1, 512>>>();
    scan3<<<nb_node, 256>>>();
    fill_csr<<<nb_edge, TPB>>>(e32);

    // ---- Phase A: GCN ----
    zero_stats<<<1, 256>>>();
    gather_gcn<<<nb_warp_node, TPB>>>();
    prep_norm<<<1, 128>>>(b1, gn_w, gn_b, gn_ms);

    // ---- Phase B: GAT (gemm_B fuses finalize_A into its loader) ----
    split_W<<<64, 256>>>(Wg);
    gemm_tf32_B<<<gemm_blocks, 256>>>(x);
    attndot<<<nb_warp_node, TPB>>>(att_src, att_dst);
    zero_stats<<<1, 256>>>();
    gather_gat<<<nb_warp_node, TPB>>>();
    prep_norm<<<1, 128>>>(bg, gn_w, gn_b, gn_ms);
    finalize_B<<<nb_elem, TPB>>>(out);
}